// round 2
// baseline (speedup 1.0000x reference)
#include <cuda_runtime.h>

#define NV   2000000
#define NC   2000
#define NE   16000
#define HID  128
#define LAT  64

// Scratch: cluster accumulators (no cudaMalloc allowed).
__device__ float g_sum[NC * 4];
__device__ float g_cnt[NC];

// ---------------------------------------------------------------------------
// Kernel 0: zero the accumulators (runs every launch -> graph-deterministic)
// ---------------------------------------------------------------------------
__global__ void k_zero() {
    int i = blockIdx.x * 256 + threadIdx.x;
    if (i < NC * 4) g_sum[i] = 0.f;
    if (i < NC)     g_cnt[i] = 0.f;
}

// ---------------------------------------------------------------------------
// Kernel 1: segment sum with shared-memory privatization.
// Each block accumulates its voxel slice into 40KB of shared bins
// (shared atomicAdd, addresses spread over 2000 clusters), then flushes
// nonzero bins to global with one atomicAdd each.
// ---------------------------------------------------------------------------
__global__ __launch_bounds__(256) void k_seg(const float* __restrict__ data,
                                             const int*   __restrict__ cid) {
    __shared__ float s_sum[NC * 4];
    __shared__ float s_cnt[NC];
    for (int i = threadIdx.x; i < NC * 4; i += 256) s_sum[i] = 0.f;
    for (int i = threadIdx.x; i < NC;     i += 256) s_cnt[i] = 0.f;
    __syncthreads();

    const int stride = gridDim.x * 256;
    for (int i = blockIdx.x * 256 + threadIdx.x; i < NV; i += stride) {
        int c = cid[i];
        const float* r = data + (size_t)i * 5;
        float f0 = __ldg(r + 1);
        float f1 = __ldg(r + 2);
        float f2 = __ldg(r + 3);
        float f3 = __ldg(r + 4);
        atomicAdd(&s_sum[c * 4 + 0], f0);
        atomicAdd(&s_sum[c * 4 + 1], f1);
        atomicAdd(&s_sum[c * 4 + 2], f2);
        atomicAdd(&s_sum[c * 4 + 3], f3);
        atomicAdd(&s_cnt[c], 1.f);
    }
    __syncthreads();

    for (int i = threadIdx.x; i < NC * 4; i += 256) {
        float v = s_sum[i];
        if (v != 0.f) atomicAdd(&g_sum[i], v);
    }
    for (int i = threadIdx.x; i < NC; i += 256) {
        float v = s_cnt[i];
        if (v != 0.f) atomicAdd(&g_cnt[i], v);
    }
}

// ---------------------------------------------------------------------------
// Kernel 2: edge gather + 2-layer MLP.
// One block = 64 edges, 128 threads.
//  Phase A: h[k][e] = relu(b1[k] + pooled[e] . W1[:,k])  (k-major in shared)
//  Phase B: register-tiled GEMM  out[e][n] = h[e][:] . W2[:,n] + b2[n]
//           thread tile = 8 edges x 4 outs, float4 shared loads.
// ---------------------------------------------------------------------------
__global__ __launch_bounds__(128) void k_mlp(const int*   __restrict__ eidx,
                                             const float* __restrict__ W1,
                                             const float* __restrict__ b1,
                                             const float* __restrict__ W2,
                                             const float* __restrict__ b2,
                                             float*       __restrict__ out) {
    extern __shared__ float sm[];
    float* s_W2   = sm;                 // 8192 floats  [128][64]
    float* s_h    = sm + 8192;          // 8192 floats  [128][64] (k-major)
    float* s_W1   = sm + 16384;         // 512 floats   [4][128]
    float* s_b1   = s_W1 + 512;         // 128
    float* s_b2   = s_b1 + 128;         // 64
    float* s_pool = s_b2 + 64;          // 256 floats   [64][4]

    const int t = threadIdx.x;

    // Load weights to shared (vectorized).
    for (int i = t; i < 8192 / 4; i += 128)
        ((float4*)s_W2)[i] = ((const float4*)W2)[i];
    for (int i = t; i < 512 / 4; i += 128)
        ((float4*)s_W1)[i] = ((const float4*)W1)[i];
    if (t < 128) s_b1[t] = b1[t];
    if (t < 64)  s_b2[t] = b2[t];

    const int base = blockIdx.x * 64;

    // Gather + pool (threads 0..63, one edge each).
    if (t < 64) {
        int e  = base + t;
        int a  = eidx[e];
        int b  = eidx[NE + e];
        float cnt = g_cnt[a] + g_cnt[b];
        float inv = 1.f / fmaxf(cnt, 1.f);
#pragma unroll
        for (int c = 0; c < 4; c++)
            s_pool[t * 4 + c] = (g_sum[a * 4 + c] + g_sum[b * 4 + c]) * inv;
    }
    __syncthreads();

    // Phase A: thread t -> edge e = t&63, k-half = (t>>6)*64.
    {
        int e  = t & 63;
        int kh = (t >> 6) * 64;
        float p0 = s_pool[e * 4 + 0];
        float p1 = s_pool[e * 4 + 1];
        float p2 = s_pool[e * 4 + 2];
        float p3 = s_pool[e * 4 + 3];
#pragma unroll 4
        for (int j = 0; j < 64; j++) {
            int k = kh + j;
            float h = s_b1[k]
                    + p0 * s_W1[0 * 128 + k]
                    + p1 * s_W1[1 * 128 + k]
                    + p2 * s_W1[2 * 128 + k]
                    + p3 * s_W1[3 * 128 + k];
            s_h[k * 64 + e] = fmaxf(h, 0.f);  // coalesced, conflict-free
        }
    }
    __syncthreads();

    // Phase B: tx = out group (4 cols), ty = edge group (8 rows).
    const int tx = t & 15;
    const int ty = t >> 4;
    float acc[8][4];
#pragma unroll
    for (int i = 0; i < 8; i++)
#pragma unroll
        for (int j = 0; j < 4; j++) acc[i][j] = 0.f;

    const float4* hf4 = (const float4*)s_h;    // [128][16]
    const float4* wf4 = (const float4*)s_W2;   // [128][16]
#pragma unroll 2
    for (int k = 0; k < 128; k++) {
        float4 w  = wf4[k * 16 + tx];          // conflict-free
        float4 ha = hf4[k * 16 + ty * 2];      // broadcast within half-warp
        float4 hb = hf4[k * 16 + ty * 2 + 1];
        float hv[8] = {ha.x, ha.y, ha.z, ha.w, hb.x, hb.y, hb.z, hb.w};
#pragma unroll
        for (int i = 0; i < 8; i++) {
            acc[i][0] = fmaf(hv[i], w.x, acc[i][0]);
            acc[i][1] = fmaf(hv[i], w.y, acc[i][1]);
            acc[i][2] = fmaf(hv[i], w.z, acc[i][2]);
            acc[i][3] = fmaf(hv[i], w.w, acc[i][3]);
        }
    }

    float c0 = s_b2[tx * 4 + 0];
    float c1 = s_b2[tx * 4 + 1];
    float c2 = s_b2[tx * 4 + 2];
    float c3 = s_b2[tx * 4 + 3];
#pragma unroll
    for (int i = 0; i < 8; i++) {
        int e = base + ty * 8 + i;
        float4 o = make_float4(acc[i][0] + c0, acc[i][1] + c1,
                               acc[i][2] + c2, acc[i][3] + c3);
        ((float4*)out)[e * 16 + tx] = o;       // coalesced float4 store
    }
}

// ---------------------------------------------------------------------------
// Launch: zero -> segment sum -> edge MLP (same stream, graph-capturable)
// ---------------------------------------------------------------------------
extern "C" void kernel_launch(void* const* d_in, const int* in_sizes, int n_in,
                              void* d_out, int out_size) {
    const float* data = (const float*)d_in[0];
    const int*   cid  = (const int*)  d_in[1];
    const int*   eidx = (const int*)  d_in[2];
    const float* W1   = (const float*)d_in[3];
    const float* b1   = (const float*)d_in[4];
    const float* W2   = (const float*)d_in[5];
    const float* b2   = (const float*)d_in[6];
    float*       out  = (float*)d_out;

    // Idempotent; safe during capture (not a stream operation).
    cudaFuncSetAttribute(k_mlp, cudaFuncAttributeMaxDynamicSharedMemorySize, 70000);

    k_zero<<<(NC * 4 + 255) / 256, 256>>>();
    k_seg<<<296, 256>>>(data, cid);
    k_mlp<<<NE / 64, 128, 69376>>>(eidx, W1, b1, W2, b2, out);
}